// round 10
// baseline (speedup 1.0000x reference)
#include <cuda_runtime.h>
#include <cstdint>

#define M 8192
#define NW 128          // 64-bit words per row (M/64)
#define NMS_T 0.3f
#define CH 256          // scan chunk size (elements)
#define WPC 4           // words per chunk (CH/64)
#define TILE 2048       // sort tile size
#define NTILE 4         // number of sort tiles (M/TILE)

typedef unsigned long long u64;

// ---------------- device scratch (no runtime allocation allowed) ------------
__device__ float  g_d[M * 5];        // transformed detections (orig order)
__device__ u64    g_ckey[M];         // packed (key<<13 | idx), padded to 8192
__device__ int    g_cnt;             // valid count (atomic; reset by scan)
__device__ int    g_V;               // valid count (published by lsort)
__device__ float  g_ds[M * 5];       // sorted detections (first V rows)
__device__ float4 g_boxes[M];        // x1,y1,x2,y2 (sorted order, first V)
__device__ u64    g_mask[M * NW];    // suppression bitmask (i>j bits only)

// ---------------- kernel 1: transform + score + compact (coalesced) ---------
__global__ void __launch_bounds__(256)
prep_kernel(const float* __restrict__ det, const float* __restrict__ off,
            const float* __restrict__ scl, const float* __restrict__ bnd) {
    __shared__ float srow[256 * 5];
    int b = blockIdx.x;                    // 32 blocks x 256 rows
    int tid = threadIdx.x;
    int lane = tid & 31;
    const float* src = det + b * 256 * 5;
    for (int i = tid; i < 256 * 5; i += 256) srow[i] = src[i];
    __syncthreads();

    int i = b * 256 + tid;                 // global row
    int w = i >> 10;
    float a0 = srow[tid * 5 + 0], a1 = srow[tid * 5 + 1], a2 = srow[tid * 5 + 2];
    float a3 = srow[tid * 5 + 3], a4 = srow[tid * 5 + 4];
    float d0 = off[w * 5 + 0] + a0 * scl[w * 5 + 0];
    float d1 = off[w * 5 + 1] + a1 * scl[w * 5 + 1];
    float d2 = off[w * 5 + 2] + a2 * scl[w * 5 + 2];
    float d3 = off[w * 5 + 3] + a3 * scl[w * 5 + 3];
    float d4 = off[w * 5 + 4] + a4 * scl[w * 5 + 4];
    bool valid = (a1 < bnd[w * 4 + 1]) && (a1 > bnd[w * 4 + 0]) &&
                 (a2 < bnd[w * 4 + 3]) && (a2 > bnd[w * 4 + 2]);

    g_d[i * 5 + 0] = d0;
    g_d[i * 5 + 1] = d1;
    g_d[i * 5 + 2] = d2;
    g_d[i * 5 + 3] = d3;
    g_d[i * 5 + 4] = d4;

    bool take = valid && d0 > 0.0f;        // non-positive scores -> zero rows
    unsigned ball = __ballot_sync(0xffffffffu, take);
    if (ball) {
        int nb = __popc(ball);
        int leader = __ffs(ball) - 1;
        int base = 0;
        if (lane == leader) base = atomicAdd(&g_cnt, nb);
        base = __shfl_sync(0xffffffffu, base, leader);
        if (take) {
            int o = __popc(ball & ((1u << lane) - 1));
            unsigned key = ~(__float_as_uint(d0) | 0x80000000u);
            g_ckey[base + o] = ((u64)key << 13) | (u64)i;  // (score desc, idx asc)
        }
    }
}

// ---------------- kernel 2a: local bitonic sort of 2048-tiles ---------------
__global__ void __launch_bounds__(1024) lsort_kernel() {
    __shared__ u64 sv[TILE];
    int tb = blockIdx.x << 11;
    int tid = threadIdx.x;
    int V = g_cnt;
    if (tb == 0 && tid == 0) g_V = V;

    if (tb >= V) {                         // pure padding tile: just materialize
        g_ckey[tb + tid] = ~0ull;
        g_ckey[tb + tid + 1024] = ~0ull;
        return;
    }

    u64 r0 = (tb + tid < V) ? g_ckey[tb + tid] : ~0ull;
    u64 r1 = (tb + tid + 1024 < V) ? g_ckey[tb + tid + 1024] : ~0ull;

    // phase A: k = 2..32 entirely in registers (intra-warp shuffles)
    int e0 = tb + tid, e1 = tb + 1024 + tid;
#pragma unroll
    for (int k = 2; k <= 32; k <<= 1) {
#pragma unroll
        for (int s = k >> 1; s >= 1; s >>= 1) {
            u64 o0 = __shfl_xor_sync(0xffffffffu, r0, s);
            u64 o1 = __shfl_xor_sync(0xffffffffu, r1, s);
            bool m0 = (((e0 & s) == 0) == ((e0 & k) == 0));
            bool m1 = (((e1 & s) == 0) == ((e1 & k) == 0));
            r0 = ((r0 < o0) == m0) ? r0 : o0;
            r1 = ((r1 < o1) == m1) ? r1 : o1;
        }
    }
    sv[tid] = r0;
    sv[tid + 1024] = r1;
    __syncthreads();

    // phase B: k = 64..2048 (strides >=32 in smem, <=16 via shuffles)
#pragma unroll
    for (int k = 64; k <= TILE; k <<= 1) {
        for (int s = k >> 1; s >= 32; s >>= 1) {
            int a = ((tid & ~(s - 1)) << 1) | (tid & (s - 1));
            bool up = (((tb + a) & k) == 0);
            u64 x = sv[a], y = sv[a + s];
            if ((x > y) == up) { sv[a] = y; sv[a + s] = x; }
            __syncthreads();
        }
        r0 = sv[tid];
        r1 = sv[tid + 1024];
#pragma unroll
        for (int s = 16; s >= 1; s >>= 1) {
            u64 o0 = __shfl_xor_sync(0xffffffffu, r0, s);
            u64 o1 = __shfl_xor_sync(0xffffffffu, r1, s);
            bool m0 = (((e0 & s) == 0) == ((e0 & k) == 0));
            bool m1 = (((e1 & s) == 0) == ((e1 & k) == 0));
            r0 = ((r0 < o0) == m0) ? r0 : o0;
            r1 = ((r1 < o1) == m1) ? r1 : o1;
        }
        if (k < TILE) {
            sv[tid] = r0;
            sv[tid + 1024] = r1;
            __syncthreads();
        }
    }
    g_ckey[tb + tid] = r0;
    g_ckey[tb + 1024 + tid] = r1;
}

// ---------------- kernel 2b: global compare-exchange stage ------------------
__global__ void __launch_bounds__(512) gmerge_kernel(int k, int s) {
    int v = blockIdx.x * 512 + threadIdx.x;       // 4096 pairs
    int a = ((v & ~(s - 1)) << 1) | (v & (s - 1));
    int b = a + s;
    bool up = ((a & k) == 0);
    u64 x = g_ckey[a], y = g_ckey[b];
    if ((x > y) == up) { g_ckey[a] = y; g_ckey[b] = x; }
}

// ---------------- kernel 2c: intra-tile merge (strides <=1024) --------------
template <int K, bool FINAL>
__global__ void __launch_bounds__(1024) lmerge_kernel() {
    __shared__ u64 sv[TILE];
    int tb = blockIdx.x << 11;
    int tid = threadIdx.x;
    sv[tid] = g_ckey[tb + tid];
    sv[tid + 1024] = g_ckey[tb + tid + 1024];
    __syncthreads();

    for (int s = 1024; s >= 32; s >>= 1) {
        int a = ((tid & ~(s - 1)) << 1) | (tid & (s - 1));
        bool up = (((tb + a) & K) == 0);
        u64 x = sv[a], y = sv[a + s];
        if ((x > y) == up) { sv[a] = y; sv[a + s] = x; }
        __syncthreads();
    }
    u64 r0 = sv[tid], r1 = sv[tid + 1024];
    int e0 = tb + tid, e1 = tb + 1024 + tid;
#pragma unroll
    for (int s = 16; s >= 1; s >>= 1) {
        u64 o0 = __shfl_xor_sync(0xffffffffu, r0, s);
        u64 o1 = __shfl_xor_sync(0xffffffffu, r1, s);
        bool m0 = (((e0 & s) == 0) == ((e0 & K) == 0));
        bool m1 = (((e1 & s) == 0) == ((e1 & K) == 0));
        r0 = ((r0 < o0) == m0) ? r0 : o0;
        r1 = ((r1 < o1) == m1) ? r1 : o1;
    }

    if (FINAL) {
        sv[tid] = r0;
        sv[tid + 1024] = r1;
        __syncthreads();
        // fused gather: build sorted rows + boxes for this tile
        int V = g_V;
        for (int l = tid; l < TILE; l += 1024) {
            int j = tb + l;
            if (j < V) {
                int idx = (int)(sv[l] & 0x1FFFu);
                float dd[5];
#pragma unroll
                for (int c = 0; c < 5; c++) {
                    dd[c] = g_d[idx * 5 + c];
                    g_ds[j * 5 + c] = dd[c];
                }
                g_boxes[j] = make_float4(dd[1] - 0.5f * dd[3], dd[2] - 0.5f * dd[4],
                                         dd[1] + 0.5f * dd[3], dd[2] + 0.5f * dd[4]);
            }
        }
    } else {
        g_ckey[tb + tid] = r0;
        g_ckey[tb + 1024 + tid] = r1;
    }
}

// ---------------- kernel 3: IoU suppression bitmask (64x64 tiles) -----------
__global__ void mask_kernel() {
    int bx = blockIdx.x, by = blockIdx.y;
    if (bx < by) return;                       // only i > j bits needed
    int V = g_V;
    if ((by << 6) >= V || (bx << 6) >= V) return;

    __shared__ float4 cbox[64];
    __shared__ float  carea[64];
    int t = threadIdx.x;
    int ci = (bx << 6) + t;
    if (ci < V) {
        cbox[t] = g_boxes[ci];
        float4 cb = cbox[t];
        carea[t] = fmaxf(cb.z - cb.x, 0.f) * fmaxf(cb.w - cb.y, 0.f);
    } else {
        cbox[t] = make_float4(0.f, 0.f, 0.f, 0.f);
        carea[t] = 0.f;
    }
    __syncthreads();

    int j = (by << 6) + t;
    if (j >= V) return;
    float4 rb = g_boxes[j];
    float  ra = fmaxf(rb.z - rb.x, 0.f) * fmaxf(rb.w - rb.y, 0.f);

    u64 bits = 0ull;
#pragma unroll
    for (int b = 0; b < 64; b++) {
        int i = (bx << 6) + b;
        if (i > j) {
            float iw = fmaxf(fminf(rb.z, cbox[b].z) - fmaxf(rb.x, cbox[b].x), 0.f);
            float ih = fmaxf(fminf(rb.w, cbox[b].w) - fmaxf(rb.y, cbox[b].y), 0.f);
            float inter = iw * ih;
            float uni = ra + carea[b] - inter;
            if (inter > NMS_T * fmaxf(uni, 1e-9f)) bits |= (1ull << b);
        }
    }
    g_mask[(size_t)j * NW + bx] = bits;
}

// ---------------- kernel 4: greedy NMS scan (speculative) + fused output ----
__global__ void __launch_bounds__(512) scan_kernel(float* __restrict__ out) {
    __shared__ u64 remv[NW];
    __shared__ u64 skeep[NW];
    __shared__ u64 sdiag[CH][WPC];        // 8KB diagonal block
    __shared__ u64 part[512];
    __shared__ unsigned short klist[CH];
    __shared__ int knum;
    int t = threadIdx.x;
    int V = g_V;
    int NC = (V + CH - 1) / CH;
    int NWv = (V + 63) >> 6;

    if (t == 511) g_cnt = 0;              // deterministic reset for next replay
    if (t < NW) { remv[t] = 0ull; skeep[t] = 0ull; }
    part[t] = 0ull;

    // prefetch diag block of chunk 0 (row = i>>2, word = i&3)
    u64 d0 = 0ull, d1 = 0ull;
    if (NC > 0) {
        d0 = g_mask[(size_t)(t >> 2) * NW + (t & 3)];
        d1 = g_mask[(size_t)((t + 512) >> 2) * NW + ((t + 512) & 3)];
    }
    __syncthreads();

    for (int c = 0; c < NC; c++) {
        sdiag[t >> 2][t & 3] = d0;
        sdiag[(t + 512) >> 2][(t + 512) & 3] = d1;
        // fold prev chunk's propagation partials into remv (word c*WPC + t)
        if (t < NW) {
            int w = c * WPC + t;
            if (w < NW)
                remv[w] |= (part[t * 4] | part[t * 4 + 1]) |
                           (part[t * 4 + 2] | part[t * 4 + 3]);
        }
        __syncthreads();

        // prefetch next chunk's diag block
        if (c + 1 < NC) {
            int base = (c + 1) * CH;
            d0 = g_mask[(size_t)(base + (t >> 2)) * NW + ((c + 1) * WPC + (t & 3))];
            d1 = g_mask[(size_t)(base + ((t + 512) >> 2)) * NW +
                        ((c + 1) * WPC + ((t + 512) & 3))];
        }

        if (t == 0) {
            u64 alive[WPC], kept[WPC];
#pragma unroll
            for (int u = 0; u < WPC; u++) {
                int rb = V - ((c * WPC + u) << 6);
                u64 vm = (rb >= 64) ? ~0ull : (rb <= 0 ? 0ull : ((1ull << rb) - 1ull));
                alive[u] = ~remv[c * WPC + u] & vm;
                kept[u] = 0ull;
            }
            int n = 0;
            int rr = -1;
#pragma unroll
            for (int u = WPC - 1; u >= 0; u--)
                if (alive[u]) rr = (u << 6) + __ffsll((long long)alive[u]) - 1;

            bool have = false;
            u64 p0 = 0, p1 = 0, p2 = 0, p3 = 0;
            while (rr >= 0) {
                u64 r0, r1, r2, r3;
                if (have) { r0 = p0; r1 = p1; r2 = p2; r3 = p3; }
                else { r0 = sdiag[rr][0]; r1 = sdiag[rr][1];
                       r2 = sdiag[rr][2]; r3 = sdiag[rr][3]; }
                int wrr = rr >> 6;
                u64 brr = 1ull << (rr & 63);
                // clear rr from alive (pre-row state)
#pragma unroll
                for (int u = 0; u < WPC; u++) if (u == wrr) alive[u] &= ~brr;
                // speculative next kept (independent of row(rr) contents)
                int rs = -1;
#pragma unroll
                for (int u = WPC - 1; u >= 0; u--)
                    if (alive[u]) rs = (u << 6) + __ffsll((long long)alive[u]) - 1;
                if (rs >= 0) { p0 = sdiag[rs][0]; p1 = sdiag[rs][1];
                               p2 = sdiag[rs][2]; p3 = sdiag[rs][3]; }
                // commit rr
#pragma unroll
                for (int u = 0; u < WPC; u++) if (u == wrr) kept[u] |= brr;
                klist[n++] = (unsigned short)rr;
                // apply suppression row
                alive[0] &= ~r0; alive[1] &= ~r1; alive[2] &= ~r2; alive[3] &= ~r3;
                // speculation check: did rs survive row(rr)?
                if (rs >= 0) {
                    u64 x = 0;
                    int ws = rs >> 6;
#pragma unroll
                    for (int u = 0; u < WPC; u++) if (u == ws) x = alive[u];
                    if ((x >> (rs & 63)) & 1ull) { rr = rs; have = true; continue; }
                }
                rr = -1;
#pragma unroll
                for (int u = WPC - 1; u >= 0; u--)
                    if (alive[u]) rr = (u << 6) + __ffsll((long long)alive[u]) - 1;
                have = false;
            }
#pragma unroll
            for (int u = 0; u < WPC; u++) skeep[c * WPC + u] = kept[u];
            knum = n;
        }
        __syncthreads();

        // propagation: 4 threads per word, 8 accumulators (MLP 32/word)
        {
            int w = (c + 1) * WPC + (t >> 2);
            int sub = t & 3;
            u64 a0 = 0, a1 = 0, a2 = 0, a3 = 0, a4 = 0, a5 = 0, a6 = 0, a7 = 0;
            if (w < NWv) {
                const u64* bp = g_mask + (size_t)(c * CH) * NW + w;
                int n = knum;
                int i = sub;
                for (; i + 28 < n; i += 32) {
                    a0 |= bp[(size_t)klist[i] * NW];
                    a1 |= bp[(size_t)klist[i + 4] * NW];
                    a2 |= bp[(size_t)klist[i + 8] * NW];
                    a3 |= bp[(size_t)klist[i + 12] * NW];
                    a4 |= bp[(size_t)klist[i + 16] * NW];
                    a5 |= bp[(size_t)klist[i + 20] * NW];
                    a6 |= bp[(size_t)klist[i + 24] * NW];
                    a7 |= bp[(size_t)klist[i + 28] * NW];
                }
                for (; i < n; i += 4) a0 |= bp[(size_t)klist[i] * NW];
            }
            part[t] = ((a0 | a1) | (a2 | a3)) | ((a4 | a5) | (a6 | a7));
        }
        __syncthreads();
    }

    // fused masked output
    for (int j = t; j < M; j += 512) {
        if (j < V) {
            float f = ((skeep[j >> 6] >> (j & 63)) & 1ull) ? 1.0f : 0.0f;
#pragma unroll
            for (int c5 = 0; c5 < 5; c5++)
                out[j * 5 + c5] = g_ds[j * 5 + c5] * f;
        } else {
#pragma unroll
            for (int c5 = 0; c5 < 5; c5++)
                out[j * 5 + c5] = 0.0f;
        }
    }
}

// ---------------- launcher ---------------------------------------------------
extern "C" void kernel_launch(void* const* d_in, const int* in_sizes, int n_in,
                              void* d_out, int out_size) {
    const float* det = (const float*)d_in[0];
    const float* off = (const float*)d_in[1];
    const float* scl = (const float*)d_in[2];
    const float* bnd = (const float*)d_in[3];
    float* out = (float*)d_out;

    prep_kernel<<<32, 256>>>(det, off, scl, bnd);
    lsort_kernel<<<NTILE, 1024>>>();
    gmerge_kernel<<<8, 512>>>(4096, 2048);      // k=4096 global stage
    lmerge_kernel<4096, false><<<NTILE, 1024>>>();
    gmerge_kernel<<<8, 512>>>(8192, 4096);      // k=8192 global stages
    gmerge_kernel<<<8, 512>>>(8192, 2048);
    lmerge_kernel<8192, true><<<NTILE, 1024>>>();
    mask_kernel<<<dim3(NW, NW), 64>>>();
    scan_kernel<<<1, 512>>>(out);
}

// round 11
// speedup vs baseline: 1.3127x; 1.3127x over previous
#include <cuda_runtime.h>
#include <cstdint>

#define M 8192
#define NW 128          // 64-bit words per row (M/64)
#define NMS_T 0.3f
#define CH 256          // scan chunk size (elements)
#define WPC 4           // words per chunk (CH/64)
#define TILE 2048       // sort tile size
#define NTILE 4         // number of sort tiles (M/TILE)

typedef unsigned long long u64;

// ---------------- device scratch (no runtime allocation allowed) ------------
__device__ float  g_d[M * 5];        // transformed detections (orig order)
__device__ u64    g_ckey[M];         // packed (key<<13 | idx), padded to 8192
__device__ int    g_cnt;             // valid count (atomic; reset by scan)
__device__ int    g_V;               // valid count (published by lsort)
__device__ float  g_ds[M * 5];       // sorted detections (first V rows)
__device__ float4 g_boxes[M];        // x1,y1,x2,y2 (sorted order, first V)
__device__ u64    g_mask[M * NW];    // suppression bitmask (i>j bits only)

// ---------------- kernel 1: transform + score + compact (coalesced) ---------
__global__ void __launch_bounds__(256)
prep_kernel(const float* __restrict__ det, const float* __restrict__ off,
            const float* __restrict__ scl, const float* __restrict__ bnd) {
    __shared__ float srow[256 * 5];
    int b = blockIdx.x;                    // 32 blocks x 256 rows
    int tid = threadIdx.x;
    int lane = tid & 31;
    const float* src = det + b * 256 * 5;
    for (int i = tid; i < 256 * 5; i += 256) srow[i] = src[i];
    __syncthreads();

    int i = b * 256 + tid;                 // global row
    int w = i >> 10;
    float a0 = srow[tid * 5 + 0], a1 = srow[tid * 5 + 1], a2 = srow[tid * 5 + 2];
    float a3 = srow[tid * 5 + 3], a4 = srow[tid * 5 + 4];
    float d0 = off[w * 5 + 0] + a0 * scl[w * 5 + 0];
    float d1 = off[w * 5 + 1] + a1 * scl[w * 5 + 1];
    float d2 = off[w * 5 + 2] + a2 * scl[w * 5 + 2];
    float d3 = off[w * 5 + 3] + a3 * scl[w * 5 + 3];
    float d4 = off[w * 5 + 4] + a4 * scl[w * 5 + 4];
    bool valid = (a1 < bnd[w * 4 + 1]) && (a1 > bnd[w * 4 + 0]) &&
                 (a2 < bnd[w * 4 + 3]) && (a2 > bnd[w * 4 + 2]);

    g_d[i * 5 + 0] = d0;
    g_d[i * 5 + 1] = d1;
    g_d[i * 5 + 2] = d2;
    g_d[i * 5 + 3] = d3;
    g_d[i * 5 + 4] = d4;

    bool take = valid && d0 > 0.0f;        // non-positive scores -> zero rows
    unsigned ball = __ballot_sync(0xffffffffu, take);
    if (ball) {
        int nb = __popc(ball);
        int leader = __ffs(ball) - 1;
        int base = 0;
        if (lane == leader) base = atomicAdd(&g_cnt, nb);
        base = __shfl_sync(0xffffffffu, base, leader);
        if (take) {
            int o = __popc(ball & ((1u << lane) - 1));
            unsigned key = ~(__float_as_uint(d0) | 0x80000000u);
            g_ckey[base + o] = ((u64)key << 13) | (u64)i;  // (score desc, idx asc)
        }
    }
}

// ---------------- kernel 2a: local bitonic sort of 2048-tiles ---------------
__global__ void __launch_bounds__(1024) lsort_kernel() {
    __shared__ u64 sv[TILE];
    int tb = blockIdx.x << 11;
    int tid = threadIdx.x;
    int V = g_cnt;
    if (tb == 0 && tid == 0) g_V = V;

    if (tb >= V) {                         // pure padding tile: just materialize
        g_ckey[tb + tid] = ~0ull;
        g_ckey[tb + tid + 1024] = ~0ull;
        return;
    }

    u64 r0 = (tb + tid < V) ? g_ckey[tb + tid] : ~0ull;
    u64 r1 = (tb + tid + 1024 < V) ? g_ckey[tb + tid + 1024] : ~0ull;

    // phase A: k = 2..32 entirely in registers (intra-warp shuffles)
    int e0 = tb + tid, e1 = tb + 1024 + tid;
#pragma unroll
    for (int k = 2; k <= 32; k <<= 1) {
#pragma unroll
        for (int s = k >> 1; s >= 1; s >>= 1) {
            u64 o0 = __shfl_xor_sync(0xffffffffu, r0, s);
            u64 o1 = __shfl_xor_sync(0xffffffffu, r1, s);
            bool m0 = (((e0 & s) == 0) == ((e0 & k) == 0));
            bool m1 = (((e1 & s) == 0) == ((e1 & k) == 0));
            r0 = ((r0 < o0) == m0) ? r0 : o0;
            r1 = ((r1 < o1) == m1) ? r1 : o1;
        }
    }
    sv[tid] = r0;
    sv[tid + 1024] = r1;
    __syncthreads();

    // phase B: k = 64..2048 (strides >=32 in smem, <=16 via shuffles)
#pragma unroll
    for (int k = 64; k <= TILE; k <<= 1) {
        for (int s = k >> 1; s >= 32; s >>= 1) {
            int a = ((tid & ~(s - 1)) << 1) | (tid & (s - 1));
            bool up = (((tb + a) & k) == 0);
            u64 x = sv[a], y = sv[a + s];
            if ((x > y) == up) { sv[a] = y; sv[a + s] = x; }
            __syncthreads();
        }
        r0 = sv[tid];
        r1 = sv[tid + 1024];
#pragma unroll
        for (int s = 16; s >= 1; s >>= 1) {
            u64 o0 = __shfl_xor_sync(0xffffffffu, r0, s);
            u64 o1 = __shfl_xor_sync(0xffffffffu, r1, s);
            bool m0 = (((e0 & s) == 0) == ((e0 & k) == 0));
            bool m1 = (((e1 & s) == 0) == ((e1 & k) == 0));
            r0 = ((r0 < o0) == m0) ? r0 : o0;
            r1 = ((r1 < o1) == m1) ? r1 : o1;
        }
        if (k < TILE) {
            sv[tid] = r0;
            sv[tid + 1024] = r1;
            __syncthreads();
        }
    }
    g_ckey[tb + tid] = r0;
    g_ckey[tb + 1024 + tid] = r1;
}

// ---------------- kernel 2b: global compare-exchange stage ------------------
__global__ void __launch_bounds__(512) gmerge_kernel(int k, int s) {
    int v = blockIdx.x * 512 + threadIdx.x;       // 4096 pairs
    int a = ((v & ~(s - 1)) << 1) | (v & (s - 1));
    int b = a + s;
    bool up = ((a & k) == 0);
    u64 x = g_ckey[a], y = g_ckey[b];
    if ((x > y) == up) { g_ckey[a] = y; g_ckey[b] = x; }
}

// ---------------- kernel 2c: intra-tile merge (strides <=1024) --------------
template <int K, bool FINAL>
__global__ void __launch_bounds__(1024) lmerge_kernel() {
    __shared__ u64 sv[TILE];
    int tb = blockIdx.x << 11;
    int tid = threadIdx.x;
    sv[tid] = g_ckey[tb + tid];
    sv[tid + 1024] = g_ckey[tb + tid + 1024];
    __syncthreads();

    for (int s = 1024; s >= 32; s >>= 1) {
        int a = ((tid & ~(s - 1)) << 1) | (tid & (s - 1));
        bool up = (((tb + a) & K) == 0);
        u64 x = sv[a], y = sv[a + s];
        if ((x > y) == up) { sv[a] = y; sv[a + s] = x; }
        __syncthreads();
    }
    u64 r0 = sv[tid], r1 = sv[tid + 1024];
    int e0 = tb + tid, e1 = tb + 1024 + tid;
#pragma unroll
    for (int s = 16; s >= 1; s >>= 1) {
        u64 o0 = __shfl_xor_sync(0xffffffffu, r0, s);
        u64 o1 = __shfl_xor_sync(0xffffffffu, r1, s);
        bool m0 = (((e0 & s) == 0) == ((e0 & K) == 0));
        bool m1 = (((e1 & s) == 0) == ((e1 & K) == 0));
        r0 = ((r0 < o0) == m0) ? r0 : o0;
        r1 = ((r1 < o1) == m1) ? r1 : o1;
    }

    if (FINAL) {
        sv[tid] = r0;
        sv[tid + 1024] = r1;
        __syncthreads();
        // fused gather: build sorted rows + boxes for this tile
        int V = g_V;
        for (int l = tid; l < TILE; l += 1024) {
            int j = tb + l;
            if (j < V) {
                int idx = (int)(sv[l] & 0x1FFFu);
                float dd[5];
#pragma unroll
                for (int c = 0; c < 5; c++) {
                    dd[c] = g_d[idx * 5 + c];
                    g_ds[j * 5 + c] = dd[c];
                }
                g_boxes[j] = make_float4(dd[1] - 0.5f * dd[3], dd[2] - 0.5f * dd[4],
                                         dd[1] + 0.5f * dd[3], dd[2] + 0.5f * dd[4]);
            }
        }
    } else {
        g_ckey[tb + tid] = r0;
        g_ckey[tb + 1024 + tid] = r1;
    }
}

// ---------------- kernel 3: IoU bitmask (256 rows x 64 cols per block) ------
__global__ void __launch_bounds__(256) mask_kernel() {
    int bx = blockIdx.x;                       // column word 0..127
    int by = blockIdx.y;                       // row tile 0..31 (256 rows each)
    int V = g_V;
    if ((by << 8) >= V || (bx << 6) >= V) return;
    if (bx < (by << 2)) return;                // tile entirely i <= j

    __shared__ float4 cbox[64];
    __shared__ float  carea[64];
    int t = threadIdx.x;
    if (t < 64) {
        int ci = (bx << 6) + t;
        float4 cb = (ci < V) ? g_boxes[ci] : make_float4(0.f, 0.f, 0.f, 0.f);
        cbox[t] = cb;
        carea[t] = fmaxf(cb.z - cb.x, 0.f) * fmaxf(cb.w - cb.y, 0.f);
    }
    __syncthreads();

    int j = (by << 8) + t;
    if (j >= V) return;
    float4 rb = g_boxes[j];
    float  ra = fmaxf(rb.z - rb.x, 0.f) * fmaxf(rb.w - rb.y, 0.f);

    u64 bits = 0ull;
#pragma unroll
    for (int b = 0; b < 64; b++) {
        int i = (bx << 6) + b;
        if (i > j) {
            float iw = fmaxf(fminf(rb.z, cbox[b].z) - fmaxf(rb.x, cbox[b].x), 0.f);
            float ih = fmaxf(fminf(rb.w, cbox[b].w) - fmaxf(rb.y, cbox[b].y), 0.f);
            float inter = iw * ih;
            float uni = ra + carea[b] - inter;
            if (inter > NMS_T * fmaxf(uni, 1e-9f)) bits |= (1ull << b);
        }
    }
    g_mask[(size_t)j * NW + bx] = bits;
}

// ---------------- kernel 4: greedy NMS scan, far-prop overlapped ------------
// per chunk: phase1 fold far partials (from chunk c-2's kept) into remv;
// phase2 greedy(c) by t0 CONCURRENT with far-prop(c-1) by threads 32..511;
// phase3 near-prop(c) into chunk c+1's words (32 thr/word + warp OR-reduce).
__global__ void __launch_bounds__(512) scan_kernel(float* __restrict__ out) {
    __shared__ u64 remv[NW];
    __shared__ u64 skeep[NW];
    __shared__ u64 sdiag[CH][WPC];             // 8KB diagonal block
    __shared__ u64 part[480];                  // far-prop partials (3/word)
    __shared__ unsigned short klist[2][CH];    // kept lists (parity buffers)
    __shared__ int knum_sh[2];
    int t = threadIdx.x;
    int V = g_V;
    int NC = (V + CH - 1) / CH;
    int NWv = (V + 63) >> 6;

    if (t == 511) g_cnt = 0;                   // deterministic reset for replay
    if (t < NW) { remv[t] = 0ull; skeep[t] = 0ull; }
    if (t < 480) part[t] = 0ull;
    if (t < 2) knum_sh[t] = 0;

    // prefetch diag block of chunk 0 (row = i>>2, word = i&3)
    u64 d0 = 0ull, d1 = 0ull;
    if (NC > 0) {
        d0 = g_mask[(size_t)(t >> 2) * NW + (t & 3)];
        d1 = g_mask[(size_t)((t + 512) >> 2) * NW + ((t + 512) & 3)];
    }
    __syncthreads();

    for (int c = 0; c < NC; c++) {
        // ---- phase 1: store diag(c); fold far partials (target words c*WPC+t)
        sdiag[t >> 2][t & 3] = d0;
        sdiag[(t + 512) >> 2][(t + 512) & 3] = d1;
        if (t < NW) {
            int w = c * WPC + t;
            if (w < NW)
                remv[w] |= (part[t * 3] | part[t * 3 + 1]) | part[t * 3 + 2];
        }
        __syncthreads();

        // ---- phase 2: diag prefetch; greedy(c) on t0; far-prop(c-1) on rest
        if (c + 1 < NC) {
            int base = (c + 1) * CH;
            d0 = g_mask[(size_t)(base + (t >> 2)) * NW + ((c + 1) * WPC + (t & 3))];
            d1 = g_mask[(size_t)(base + ((t + 512) >> 2)) * NW +
                        ((c + 1) * WPC + ((t + 512) & 3))];
        }

        if (t == 0) {
            // ---- greedy: EXACT R4/R8 loop (do not touch: spill-sensitive) ----
            u64 alive[WPC], kept[WPC];
#pragma unroll
            for (int u = 0; u < WPC; u++) {
                int rb = V - ((c * WPC + u) << 6);
                u64 vm = (rb >= 64) ? ~0ull : (rb <= 0 ? 0ull : ((1ull << rb) - 1ull));
                alive[u] = ~remv[c * WPC + u] & vm;
                kept[u] = 0ull;
            }
            int n = 0;
            for (int w = 0; w < WPC; w++) {
                while (alive[w]) {
                    int b = __ffsll((long long)alive[w]) - 1;
                    int rr = (w << 6) + b;
                    kept[w] |= 1ull << b;
                    klist[c & 1][n++] = (unsigned short)rr;
                    alive[w] &= ~(1ull << b);
                    for (int u = w; u < WPC; u++)
                        alive[u] &= ~sdiag[rr][u];
                }
            }
#pragma unroll
            for (int u = 0; u < WPC; u++) skeep[c * WPC + u] = kept[u];
            knum_sh[c & 1] = n;
        } else if (t >= 32) {
            // far-prop of chunk c-1's kept into words >= (c+1)*WPC
            int u = t - 32;                    // 0..479
            int w = (c + 1) * WPC + u / 3;
            int sub = u % 3;
            u64 a0 = 0, a1 = 0, a2 = 0, a3 = 0, a4 = 0, a5 = 0, a6 = 0, a7 = 0;
            int np = knum_sh[(c + 1) & 1];     // knum of chunk c-1 (parity)
            if (c >= 1 && w < NWv && np > 0) {
                const unsigned short* kp = klist[(c + 1) & 1];
                const u64* bp = g_mask + (size_t)((c - 1) * CH) * NW + w;
                int i = sub;
                for (; i + 21 < np; i += 24) {
                    a0 |= bp[(size_t)kp[i] * NW];
                    a1 |= bp[(size_t)kp[i + 3] * NW];
                    a2 |= bp[(size_t)kp[i + 6] * NW];
                    a3 |= bp[(size_t)kp[i + 9] * NW];
                    a4 |= bp[(size_t)kp[i + 12] * NW];
                    a5 |= bp[(size_t)kp[i + 15] * NW];
                    a6 |= bp[(size_t)kp[i + 18] * NW];
                    a7 |= bp[(size_t)kp[i + 21] * NW];
                }
                for (; i < np; i += 3) a0 |= bp[(size_t)kp[i] * NW];
            }
            part[u] = ((a0 | a1) | (a2 | a3)) | ((a4 | a5) | (a6 | a7));
        }
        __syncthreads();

        // ---- phase 3: near-prop(c) into chunk c+1's 4 words (32 thr/word)
        if (t < 128) {
            int w = (c + 1) * WPC + (t >> 5);
            int sub = t & 31;
            u64 acc = 0ull;
            int n = knum_sh[c & 1];
            bool act = (c + 1 < NC) && (w < NWv);
            if (act) {
                const unsigned short* kc = klist[c & 1];
                const u64* bp = g_mask + (size_t)(c * CH) * NW + w;
                u64 b0 = 0, b1 = 0;
                int i = sub;
                for (; i + 32 < n; i += 64) {
                    b0 |= bp[(size_t)kc[i] * NW];
                    b1 |= bp[(size_t)kc[i + 32] * NW];
                }
                if (i < n) b0 |= bp[(size_t)kc[i] * NW];
                acc = b0 | b1;
            }
#pragma unroll
            for (int s = 16; s >= 1; s >>= 1)
                acc |= __shfl_xor_sync(0xffffffffu, acc, s);
            if (sub == 0 && act) remv[w] |= acc;
        }
        __syncthreads();
    }

    // fused masked output
    for (int j = t; j < M; j += 512) {
        if (j < V) {
            float f = ((skeep[j >> 6] >> (j & 63)) & 1ull) ? 1.0f : 0.0f;
#pragma unroll
            for (int c5 = 0; c5 < 5; c5++)
                out[j * 5 + c5] = g_ds[j * 5 + c5] * f;
        } else {
#pragma unroll
            for (int c5 = 0; c5 < 5; c5++)
                out[j * 5 + c5] = 0.0f;
        }
    }
}

// ---------------- launcher ---------------------------------------------------
extern "C" void kernel_launch(void* const* d_in, const int* in_sizes, int n_in,
                              void* d_out, int out_size) {
    const float* det = (const float*)d_in[0];
    const float* off = (const float*)d_in[1];
    const float* scl = (const float*)d_in[2];
    const float* bnd = (const float*)d_in[3];
    float* out = (float*)d_out;

    prep_kernel<<<32, 256>>>(det, off, scl, bnd);
    lsort_kernel<<<NTILE, 1024>>>();
    gmerge_kernel<<<8, 512>>>(4096, 2048);      // k=4096 global stage
    lmerge_kernel<4096, false><<<NTILE, 1024>>>();
    gmerge_kernel<<<8, 512>>>(8192, 4096);      // k=8192 global stages
    gmerge_kernel<<<8, 512>>>(8192, 2048);
    lmerge_kernel<8192, true><<<NTILE, 1024>>>();
    mask_kernel<<<dim3(NW, 32), 256>>>();
    scan_kernel<<<1, 512>>>(out);
}